// round 14
// baseline (speedup 1.0000x reference)
#include <cuda_runtime.h>
#include <cuda_fp16.h>
#include <math.h>
#include <stdint.h>

// ---------------------------------------------------------------------------
// MultiHeadAttention: x@Wq/Wk/Wv -> causal flash attention -> @Wo
// B=4, S=2048, E=1024, H=16, Hs=64. fp32 I/O, FP16 tensor-core math.
// R14: attention S=QK^T with fp16 accumulators (2x HMMA rate if supported),
//      fully packed half2 softmax, Q-smem overlaid on K1 buffer (73.7KB),
//      3 CTAs/SM. PV + l remain fp32-accumulated. GEMMs unchanged.
// ---------------------------------------------------------------------------

#define BATCH 4
#define SEQ   2048
#define EMBD  1024
#define NHEAD 16
#define HDIM  64
#define MROWS (BATCH*SEQ)   // 8192

#define QSCALE 0.18033688011112042f   // 0.125 * log2(e)

__device__ __align__(256) __half g_Q[MROWS * EMBD];
__device__ __align__(256) __half g_K[MROWS * EMBD];
__device__ __align__(256) __half g_V[MROWS * EMBD];
__device__ __align__(256) __half g_A[MROWS * EMBD];
__device__ __align__(256) __half g_X[MROWS * EMBD];
__device__ __align__(256) __half g_W[4 * EMBD * EMBD];   // fp16, transposed [n][k]

__device__ __forceinline__ uint32_t s2u(const void* p) {
    return (uint32_t)__cvta_generic_to_shared(p);
}
#define CP16(dst, src) \
    asm volatile("cp.async.cg.shared.global [%0], [%1], 16;\n" :: "r"(dst), "l"(src))
#define CP_COMMIT()  asm volatile("cp.async.commit_group;\n" ::: "memory")
#define CP_WAIT(n)   asm volatile("cp.async.wait_group %0;\n" :: "n"(n) : "memory")

#define LDSM4(r, addr) \
    asm volatile("ldmatrix.sync.aligned.m8n8.x4.shared.b16 {%0,%1,%2,%3}, [%4];" \
        : "=r"((r)[0]), "=r"((r)[1]), "=r"((r)[2]), "=r"((r)[3]) : "r"(addr))
#define LDSM4T(r, addr) \
    asm volatile("ldmatrix.sync.aligned.m8n8.x4.trans.shared.b16 {%0,%1,%2,%3}, [%4];" \
        : "=r"((r)[0]), "=r"((r)[1]), "=r"((r)[2]), "=r"((r)[3]) : "r"(addr))

// fp32-accumulate fp16 MMA
__device__ __forceinline__ void mma16(float* c, const unsigned* a, const unsigned* b) {
    asm volatile(
        "mma.sync.aligned.m16n8k16.row.col.f32.f16.f16.f32 "
        "{%0,%1,%2,%3}, {%4,%5,%6,%7}, {%8,%9}, {%0,%1,%2,%3};\n"
        : "+f"(c[0]), "+f"(c[1]), "+f"(c[2]), "+f"(c[3])
        : "r"(a[0]), "r"(a[1]), "r"(a[2]), "r"(a[3]),
          "r"(b[0]), "r"(b[1]));
}

// fp16-accumulate fp16 MMA (C/D = 2 packed b32 regs)
__device__ __forceinline__ void mma16h(unsigned* c, const unsigned* a, const unsigned* b) {
    asm volatile(
        "mma.sync.aligned.m16n8k16.row.col.f16.f16.f16.f16 "
        "{%0,%1}, {%2,%3,%4,%5}, {%6,%7}, {%0,%1};\n"
        : "+r"(c[0]), "+r"(c[1])
        : "r"(a[0]), "r"(a[1]), "r"(a[2]), "r"(a[3]),
          "r"(b[0]), "r"(b[1]));
}

__device__ __forceinline__ unsigned pack_h2(float lo, float hi) {
    __half2 h = __floats2half2_rn(lo, hi);
    return *(unsigned*)&h;
}

__device__ __forceinline__ unsigned hex2(unsigned x) {
    unsigned y;
    asm("ex2.approx.f16x2 %0, %1;" : "=r"(y) : "r"(x));
    return y;
}

__device__ __forceinline__ unsigned hmax2u(unsigned a, unsigned b) {
    __half2 r = __hmax2(*(__half2*)&a, *(__half2*)&b);
    return *(unsigned*)&r;
}
__device__ __forceinline__ unsigned hsub2u(unsigned a, unsigned b) {
    __half2 r = __hsub2(*(__half2*)&a, *(__half2*)&b);
    return *(unsigned*)&r;
}

// ---------------------------------------------------------------------------
// Merged pre-pass: x -> fp16; weights round+transpose to fp16 [n][k]
// ---------------------------------------------------------------------------
#define XBLKS 8192
__global__ __launch_bounds__(256) void prep(
    const float4* __restrict__ x, uint2* __restrict__ xout,
    const float* __restrict__ w0, const float* __restrict__ w1,
    const float* __restrict__ w2, const float* __restrict__ w3,
    __half* __restrict__ wout)
{
    __shared__ float t[32][33];
    const int bid = blockIdx.x;
    if (bid < XBLKS) {
        int i = bid * 256 + threadIdx.x;
        float4 v = x[i];
        xout[i] = make_uint2(pack_h2(v.x, v.y), pack_h2(v.z, v.w));
    } else {
        const int wid = bid - XBLKS;
        const int z   = wid >> 10;
        const int rem = wid & 1023;
        const int bx  = (rem & 31) * 32;
        const int by  = (rem >> 5) * 32;
        const float* in = (z == 0) ? w0 : (z == 1) ? w1 : (z == 2) ? w2 : w3;
        __half* o = wout + (size_t)z * EMBD * EMBD;
        int tx = threadIdx.x & 31, ty = threadIdx.x >> 5;
        #pragma unroll
        for (int i = 0; i < 32; i += 8)
            t[ty + i][tx] = in[(size_t)(by + ty + i) * EMBD + bx + tx];
        __syncthreads();
        #pragma unroll
        for (int i = 0; i < 32; i += 8)
            o[(size_t)(bx + ty + i) * EMBD + by + tx] = __float2half_rn(t[tx][ty + i]);
    }
}

// ---------------------------------------------------------------------------
// FP16 GEMM body (unchanged). CTA 128x128, BK=64, 3-stage cp.async, LDSM.
// ---------------------------------------------------------------------------
#define RSTR 144
#define TILE_B (128 * RSTR)
#define STG_BYTES (2 * TILE_B)
#define GST 3
#define GSMEM (GST * STG_BYTES)        // 110592

template<bool HALF_OUT>
__device__ __forceinline__ void gemm_body(
    const __half* __restrict__ A, const __half* __restrict__ Bt, void* __restrict__ Cv,
    float oscale, int m0, int n0)
{
    extern __shared__ __align__(1024) unsigned char sgm[];

    const int tid  = threadIdx.x;
    const int warp = tid >> 5;
    const int lane = tid & 31;
    const int l4   = lane >> 2;
    const int lm4  = lane & 3;
    const int wm0  = (warp >> 1) * 32;
    const int wn0  = (warp & 1) * 64;

    const int lrow = lane & 15;
    const int lcol = (lane >> 4) * 16;

    float acc[2][8][4];
    #pragma unroll
    for (int mi = 0; mi < 2; mi++)
        #pragma unroll
        for (int ni = 0; ni < 8; ni++)
            #pragma unroll
            for (int q = 0; q < 4; q++) acc[mi][ni][q] = 0.0f;

    const uint32_t sbase = s2u(sgm);

    auto load_stage = [&](int s, int k0) {
        uint32_t ab = sbase + s * STG_BYTES;
        uint32_t bb = ab + TILE_B;
        #pragma unroll
        for (int t = 0; t < 4; t++) {
            int id = tid + t * 256;
            int r = id >> 3;
            int c = (id & 7) * 8;
            CP16(ab + r * RSTR + c * 2, A  + (size_t)(m0 + r) * EMBD + k0 + c);
        }
        #pragma unroll
        for (int t = 0; t < 4; t++) {
            int id = tid + t * 256;
            int r = id >> 3;
            int c = (id & 7) * 8;
            CP16(bb + r * RSTR + c * 2, Bt + (size_t)(n0 + r) * EMBD + k0 + c);
        }
        CP_COMMIT();
    };

    load_stage(0, 0);
    load_stage(1, 64);

    const int KT = EMBD / 64;  // 16
    for (int kt = 0; kt < KT; kt++) {
        const int s = kt % GST;
        if (kt < KT - 1) { CP_WAIT(1); } else { CP_WAIT(0); }
        __syncthreads();
        if (kt + 2 < KT) load_stage((kt + 2) % GST, (kt + 2) * 64);

        const uint32_t ab   = sbase + s * STG_BYTES;
        const uint32_t aoff = ab + (wm0 + lrow) * RSTR + lcol;
        const uint32_t boff = ab + TILE_B + (wn0 + lrow) * RSTR + lcol;

        #pragma unroll
        for (int kk = 0; kk < 4; kk++) {
            unsigned a0[4], a1[4];
            LDSM4(a0, aoff + kk * 32);
            LDSM4(a1, aoff + 16 * RSTR + kk * 32);
            unsigned bf[4][4];
            #pragma unroll
            for (int ng = 0; ng < 4; ng++)
                LDSM4(bf[ng], boff + ng * 16 * RSTR + kk * 32);
            #pragma unroll
            for (int ni = 0; ni < 8; ni++) {
                unsigned b2[2] = { bf[ni >> 1][ni & 1], bf[ni >> 1][(ni & 1) + 2] };
                mma16(acc[0][ni], a0, b2);
                mma16(acc[1][ni], a1, b2);
            }
        }
    }

    #pragma unroll
    for (int mi = 0; mi < 2; mi++) {
        #pragma unroll
        for (int ni = 0; ni < 8; ni++) {
            int row = m0 + wm0 + mi * 16 + l4;
            int col = n0 + wn0 + ni * 8 + lm4 * 2;
            if (HALF_OUT) {
                __half* C = (__half*)Cv;
                *(unsigned*)&C[(size_t)row * EMBD + col] =
                    pack_h2(acc[mi][ni][0] * oscale, acc[mi][ni][1] * oscale);
                *(unsigned*)&C[(size_t)(row + 8) * EMBD + col] =
                    pack_h2(acc[mi][ni][2] * oscale, acc[mi][ni][3] * oscale);
            } else {
                float* C = (float*)Cv;
                *(float2*)&C[(size_t)row * EMBD + col] =
                    make_float2(acc[mi][ni][0], acc[mi][ni][1]);
                *(float2*)&C[(size_t)(row + 8) * EMBD + col] =
                    make_float2(acc[mi][ni][2], acc[mi][ni][3]);
            }
        }
    }
}

__global__ __launch_bounds__(256, 2) void gemm_qkv(
    const __half* __restrict__ X, const __half* __restrict__ Wt,
    __half* __restrict__ C0, __half* __restrict__ C1, __half* __restrict__ C2)
{
    const int z  = blockIdx.x % 3;
    const int n0 = (blockIdx.x / 3) * 128;
    const int m0 = blockIdx.y * 128;
    const __half* Bt = Wt + (size_t)z * EMBD * EMBD;
    __half* C = (z == 0) ? C0 : (z == 1) ? C1 : C2;
    float sc = (z == 0) ? QSCALE : 1.0f;
    gemm_body<true>(X, Bt, C, sc, m0, n0);
}

__global__ __launch_bounds__(256, 2) void gemm_out(
    const __half* __restrict__ A, const __half* __restrict__ Wt, float* __restrict__ C)
{
    gemm_body<false>(A, Wt, C, 1.0f, blockIdx.y * 128, blockIdx.x * 128);
}

// ---------------------------------------------------------------------------
// Causal flash attention. One CTA = 128 q-rows, 128 threads = 4 warps x 32
// q-rows. S=QK^T in fp16 accumulators + packed half2 softmax; PV/l fp32.
// Q smem overlaid on K-buffer-1 (dead after register hoist). 3 CTAs/SM.
// ---------------------------------------------------------------------------
#define KTB (64 * RSTR)                // 9216 per 64-key subtile
#define KVBLK (2 * KTB)                // 18432: one 128-key K (or V) block
#define ATTN_SMEM (4 * KVBLK)          // 73728: K0 K1 V0 V1 (Q overlays K1)
#define HNEG2 0xFC00FC00u              // half2(-inf,-inf)
#define HONE2 0x3C003C00u              // half2(1,1)

__global__ __launch_bounds__(128, 3) void attn_flash(
    const __half* __restrict__ Q, const __half* __restrict__ K,
    const __half* __restrict__ V, __half* __restrict__ O)
{
    extern __shared__ __align__(1024) unsigned char sgm[];
    const uint32_t kbase = s2u(sgm);
    const uint32_t vbase = kbase + 2 * KVBLK;
    const uint32_t qbase = kbase + KVBLK;     // overlay: K buffer 1

    const int tid  = threadIdx.x;
    const int warp = tid >> 5;
    const int lane = tid & 31;
    const int l4   = lane >> 2;
    const int lm4  = lane & 3;
    const int w32  = warp * 32;

    const int lrow = lane & 15;
    const int lcol = (lane >> 4) * 16;

    const int qb = (gridDim.x - 1) - blockIdx.x;   // longest blocks first
    const int q0 = qb * 128;
    const int bh = blockIdx.y;
    const int b  = bh >> 4;
    const int h  = bh & 15;
    const size_t headoff = (size_t)b * SEQ * EMBD + (size_t)h * HDIM;

    // Load Q tile (128 x 64 fp16) into the K1 overlay region
    #pragma unroll
    for (int t = 0; t < 8; t++) {
        int idx = tid + t * 128;
        int r = idx >> 3;
        int c = (idx & 7) * 8;
        *(uint4*)(sgm + KVBLK + r * RSTR + c * 2) =
            *(const uint4*)(Q + headoff + (size_t)(q0 + r) * EMBD + c);
    }

    auto load_kv2 = [&](int jj, int s) {
        #pragma unroll
        for (int t = 0; t < 8; t++) {
            int id = tid + t * 128;
            int r = id >> 3;
            int c = (id & 7) * 8;
            CP16(kbase + s * KVBLK + r * RSTR + c * 2,
                 K + headoff + (size_t)(jj * 128 + r) * EMBD + c);
        }
        #pragma unroll
        for (int t = 0; t < 8; t++) {
            int id = tid + t * 128;
            int r = id >> 3;
            int c = (id & 7) * 8;
            CP16(vbase + s * KVBLK + r * RSTR + c * 2,
                 V + headoff + (size_t)(jj * 128 + r) * EMBD + c);
        }
        CP_COMMIT();
    };

    // Running max (packed: lo=row l4, hi=row l4+8), fp32 O and l accumulators
    unsigned m2[2] = { HNEG2, HNEG2 };
    float o[2][8][4];
    float lacc[2][4];
    #pragma unroll
    for (int mi = 0; mi < 2; mi++) {
        #pragma unroll
        for (int ni = 0; ni < 8; ni++)
            #pragma unroll
            for (int q = 0; q < 4; q++) o[mi][ni][q] = 0.0f;
        #pragma unroll
        for (int q = 0; q < 4; q++) lacc[mi][q] = 0.0f;
    }

    const int njj = qb + 1;
    load_kv2(0, 0);

    // Hoist Q fragments (then the Q smem region becomes K buffer 1)
    __syncthreads();
    unsigned qf[2][4][4];
    {
        const uint32_t qoff0 = qbase + (w32 + lrow) * RSTR + lcol;
        const uint32_t qoff1 = qoff0 + 16 * RSTR;
        #pragma unroll
        for (int kk = 0; kk < 4; kk++) {
            LDSM4(qf[0][kk], qoff0 + kk * 32);
            LDSM4(qf[1][kk], qoff1 + kk * 32);
        }
    }

    for (int jj = 0; jj < njj; jj++) {
        CP_WAIT(0);
        __syncthreads();                       // all warps past hoist + KV ready
        if (jj + 1 < njj) load_kv2(jj + 1, (jj + 1) & 1);

        #pragma unroll
        for (int hs = 0; hs < 2; hs++) {
            const int j = 2 * jj + hs;

            if (j * 64 > q0 + w32 + 31) continue;

            const uint32_t koff = kbase + (jj & 1) * KVBLK + hs * KTB
                                + lrow * RSTR + lcol;
            const uint32_t voff = vbase + (jj & 1) * KVBLK + hs * KTB
                                + lrow * RSTR + lcol;

            // S = Q K^T, fp16 accumulate. s_h[mi][ni] = {rows l4, rows l4+8}
            unsigned s_h[2][8][2];
            #pragma unroll
            for (int mi = 0; mi < 2; mi++)
                #pragma unroll
                for (int ni = 0; ni < 8; ni++) {
                    s_h[mi][ni][0] = 0u;
                    s_h[mi][ni][1] = 0u;
                }

            #pragma unroll
            for (int kk = 0; kk < 4; kk++) {
                unsigned bf[4][4];
                #pragma unroll
                for (int ng = 0; ng < 4; ng++)
                    LDSM4(bf[ng], koff + ng * 16 * RSTR + kk * 32);
                #pragma unroll
                for (int ni = 0; ni < 8; ni++) {
                    unsigned b2[2] = { bf[ni >> 1][ni & 1], bf[ni >> 1][(ni & 1) + 2] };
                    mma16h(s_h[0][ni], qf[0][kk], b2);
                    mma16h(s_h[1][ni], qf[1][kk], b2);
                }
            }

            // Causal mask (diag subtiles only; warp-uniform)
            if (j * 64 + 63 > q0 + w32) {
                #pragma unroll
                for (int mi = 0; mi < 2; mi++) {
                    const int g0 = q0 + w32 + mi * 16 + l4;
                    const int g1 = g0 + 8;
                    #pragma unroll
                    for (int ni = 0; ni < 8; ni++) {
                        int gc = j * 64 + ni * 8 + lm4 * 2;
                        unsigned v0 = s_h[mi][ni][0];
                        unsigned v1 = s_h[mi][ni][1];
                        if (gc     > g0) v0 = (v0 & 0xFFFF0000u) | 0x0000FC00u;
                        if (gc + 1 > g0) v0 = (v0 & 0x0000FFFFu) | 0xFC000000u;
                        if (gc     > g1) v1 = (v1 & 0xFFFF0000u) | 0x0000FC00u;
                        if (gc + 1 > g1) v1 = (v1 & 0x0000FFFFu) | 0xFC000000u;
                        s_h[mi][ni][0] = v0;
                        s_h[mi][ni][1] = v1;
                    }
                }
            }

            // Row max (packed) + online rescale
            unsigned a2[2], nmlo2[2], nmhi2[2];
            #pragma unroll
            for (int mi = 0; mi < 2; mi++) {
                unsigned r0 = s_h[mi][0][0], r1 = s_h[mi][0][1];
                #pragma unroll
                for (int ni = 1; ni < 8; ni++) {
                    r0 = hmax2u(r0, s_h[mi][ni][0]);
                    r1 = hmax2u(r1, s_h[mi][ni][1]);
                }
                __half2 h0 = *(__half2*)&r0;
                __half2 h1 = *(__half2*)&r1;
                __half2 mxh = __halves2half2(
                    __hmax(__low2half(h0), __high2half(h0)),
                    __hmax(__low2half(h1), __high2half(h1)));
                unsigned mx = *(unsigned*)&mxh;
                #pragma unroll
                for (int off = 1; off < 4; off <<= 1)
                    mx = hmax2u(mx, __shfl_xor_sync(0xffffffffu, mx, off));

                unsigned nm2 = hmax2u(m2[mi], mx);
                a2[mi] = hex2(hsub2u(m2[mi], nm2));
                m2[mi] = nm2;
                __half2 nmh = *(__half2*)&nm2;
                __half2 lo2 = __low2half2(nmh);
                __half2 hi2 = __high2half2(nmh);
                nmlo2[mi] = *(unsigned*)&lo2;
                nmhi2[mi] = *(unsigned*)&hi2;
            }

            bool noresc = (a2[0] == HONE2) && (a2[1] == HONE2);
            if (!__all_sync(0xffffffffu, noresc)) {
                #pragma unroll
                for (int mi = 0; mi < 2; mi++) {
                    float2 af = __half22float2(*(__half2*)&a2[mi]);
                    #pragma unroll
                    for (int ni = 0; ni < 8; ni++) {
                        o[mi][ni][0] *= af.x; o[mi][ni][1] *= af.x;
                        o[mi][ni][2] *= af.y; o[mi][ni][3] *= af.y;
                    }
                    lacc[mi][0] *= af.x; lacc[mi][1] *= af.x;
                    lacc[mi][2] *= af.y; lacc[mi][3] *= af.y;
                }
            }

            // P = 2^(s-m) directly from fp16 fragments; O += P@V; l += P@1
            #pragma unroll
            for (int g = 0; g < 4; g++) {
                unsigned ap[2][4];
                #pragma unroll
                for (int mi = 0; mi < 2; mi++) {
                    ap[mi][0] = hex2(hsub2u(s_h[mi][2*g][0],   nmlo2[mi]));
                    ap[mi][1] = hex2(hsub2u(s_h[mi][2*g][1],   nmhi2[mi]));
                    ap[mi][2] = hex2(hsub2u(s_h[mi][2*g+1][0], nmlo2[mi]));
                    ap[mi][3] = hex2(hsub2u(s_h[mi][2*g+1][1], nmhi2[mi]));
                }

                unsigned ones2[2] = { HONE2, HONE2 };
                mma16(lacc[0], ap[0], ones2);
                mma16(lacc[1], ap[1], ones2);

                #pragma unroll
                for (int dg = 0; dg < 4; dg++) {
                    unsigned vf[4];
                    LDSM4T(vf, voff + g * 16 * RSTR + dg * 32);
                    unsigned b0[2] = { vf[0], vf[1] };
                    unsigned b1[2] = { vf[2], vf[3] };
                    mma16(o[0][2*dg],     ap[0], b0);
                    mma16(o[0][2*dg + 1], ap[0], b1);
                    mma16(o[1][2*dg],     ap[1], b0);
                    mma16(o[1][2*dg + 1], ap[1], b1);
                }
            }
        }
    }

    // Epilogue
    #pragma unroll
    for (int mi = 0; mi < 2; mi++) {
        float i0 = 1.0f / lacc[mi][0];
        float i1 = 1.0f / lacc[mi][2];
        #pragma unroll
        for (int ni = 0; ni < 8; ni++) {
            int gr = b * SEQ + q0 + w32 + mi * 16 + l4;
            int gc = h * HDIM + ni * 8 + lm4 * 2;
            *(unsigned*)&O[(size_t)gr * EMBD + gc] =
                pack_h2(o[mi][ni][0] * i0, o[mi][ni][1] * i0);
            *(unsigned*)&O[(size_t)(gr + 8) * EMBD + gc] =
                pack_h2(o[mi][ni][2] * i1, o[mi][ni][3] * i1);
        }
    }
}

// ---------------------------------------------------------------------------
// Launch
// ---------------------------------------------------------------------------
extern "C" void kernel_launch(void* const* d_in, const int* in_sizes, int n_in,
                              void* d_out, int out_size)
{
    const float* x  = (const float*)d_in[0];
    const float* Wq = (const float*)d_in[1];
    const float* Wk = (const float*)d_in[2];
    const float* Wv = (const float*)d_in[3];
    const float* Wo = (const float*)d_in[4];
    float* out = (float*)d_out;

    __half *Qp, *Kp, *Vp, *Ap, *Xp, *Wp;
    cudaGetSymbolAddress((void**)&Qp, g_Q);
    cudaGetSymbolAddress((void**)&Kp, g_K);
    cudaGetSymbolAddress((void**)&Vp, g_V);
    cudaGetSymbolAddress((void**)&Ap, g_A);
    cudaGetSymbolAddress((void**)&Xp, g_X);
    cudaGetSymbolAddress((void**)&Wp, g_W);

    cudaFuncSetAttribute(gemm_qkv,   cudaFuncAttributeMaxDynamicSharedMemorySize, GSMEM);
    cudaFuncSetAttribute(gemm_out,   cudaFuncAttributeMaxDynamicSharedMemorySize, GSMEM);
    cudaFuncSetAttribute(attn_flash, cudaFuncAttributeMaxDynamicSharedMemorySize, ATTN_SMEM);

    prep<<<XBLKS + 4096, 256>>>((const float4*)x, (uint2*)Xp,
                                Wq, Wk, Wv, Wo, Wp);

    dim3 gqkv((EMBD / 128) * 3, MROWS / 128);   // (24, 64), z fastest
    gemm_qkv<<<gqkv, 256, GSMEM>>>(Xp, Wp, Qp, Kp, Vp);

    dim3 ga(SEQ / 128, BATCH * NHEAD);          // (16, 64)
    attn_flash<<<ga, 128, ATTN_SMEM>>>(Qp, Kp, Vp, Ap);

    dim3 go(EMBD / 128, MROWS / 128);
    gemm_out<<<go, 256, GSMEM>>>(Ap, Wp + 3 * (size_t)EMBD * EMBD, out);
}